// round 10
// baseline (speedup 1.0000x reference)
#include <cuda_runtime.h>
#include <cuda_bf16.h>
#include <cstdint>
#include <math.h>

#define N_SAMP 2048
#define DD 784
#define KR 10
#define LAYERS 32
#define KCLS 10
#define HCONST 0.001f

__device__ float g_s[N_SAMP * 100];
__device__ float g_shist[33 * N_SAMP * 100];
__device__ __nv_bfloat16 g_xh[N_SAMP * DD];
__device__ __nv_bfloat16 g_wh[33 * DD * DD];
__device__ float g_Pp[7 * N_SAMP * 280];     // partial P slabs, sample-major
__device__ int g_cnt[33 * 32];               // per (layer, bm-row) counters

// ---------------- weights -> bf16 -------------------------------------------
__global__ void wcvt_kernel(const float* __restrict__ W0, const float* __restrict__ Ws) {
    size_t idx = ((size_t)blockIdx.x * blockDim.x + threadIdx.x) * 4;
    size_t total = (size_t)33 * DD * DD;
    if (idx >= total) return;
    size_t per = (size_t)DD * DD;
    const float* src = (idx < per) ? (W0 + idx) : (Ws + (idx - per));
    float4 v = *(const float4*)src;
    __nv_bfloat16 o[4] = {__float2bfloat16(v.x), __float2bfloat16(v.y),
                          __float2bfloat16(v.z), __float2bfloat16(v.w)};
    *(uint2*)(g_wh + idx) = *(uint2*)o;
}

// ---------------- init -------------------------------------------------------
__global__ void init_kernel(const float* __restrict__ X) {
    __shared__ float u[280], vh[280], s[100], US[280];
    int i = blockIdx.x, t = threadIdx.x;
    {
        int idx = i * 256 + t;
        if (idx < 33 * 32) g_cnt[idx] = 0;
    }
    const float* xb = X + (size_t)i * 840;
    for (int k = t; k < 280; k += blockDim.x) { u[k] = xb[k]; vh[k] = xb[560 + k]; }
    for (int k = t; k < 100; k += blockDim.x) { float v = xb[280 + k]; s[k] = v; g_s[i * 100 + k] = v; }
    __syncthreads();
    for (int k = t; k < 280; k += blockDim.x) {
        int r = k / 10, b = k % 10;
        float acc = 0.f;
#pragma unroll
        for (int a = 0; a < 10; a++) acc += u[r * 10 + a] * s[a * 10 + b];
        US[k] = acc;
    }
    __syncthreads();
    for (int k = t; k < DD; k += blockDim.x) {
        int r = k / 28, c = k % 28;
        float acc = 0.f;
#pragma unroll
        for (int b = 0; b < 10; b++) acc += US[r * 10 + b] * vh[b * 28 + c];
        g_xh[(size_t)i * DD + k] = __float2bfloat16(acc);
    }
}

// ---------------- fused layer kernel ------------------------------------------
#define GBM 64
#define GBN 112
#define GBK 32
#define SPAD 40
#define NIT 25
// dynamic smem layout
#define AS_BYTES (2 * GBM * SPAD * 2)              // 10240
#define BS_BYTES (2 * GBN * SPAD * 2)              // 17920
#define AB_BYTES (AS_BYTES + BS_BYTES)             // 28160
#define ZB_STRIDE 113
#define ZB_BYTES (GBM * ZB_STRIDE * 4)             // 28928
#define US_STRIDE 41
#define USM_BYTES (GBM * US_STRIDE * 4)            // 10496
#define LAYER_SMEM (AB_BYTES + ZB_BYTES + USM_BYTES)  // 67584

__device__ __forceinline__ unsigned smem_u32(const void* p) {
    return (unsigned)__cvta_generic_to_shared(p);
}
__device__ __forceinline__ void cp16(unsigned dst, const void* src, int sz) {
    asm volatile("cp.async.cg.shared.global [%0], [%1], 16, %2;\n"
                 :: "r"(dst), "l"(src), "r"(sz));
}

__global__ __launch_bounds__(256) void layer_kernel(const float* __restrict__ X,
                                                    const __nv_bfloat16* __restrict__ W,
                                                    const float* __restrict__ bias,
                                                    int do_relu, int col) {
    extern __shared__ char dsm[];
    __nv_bfloat16 (*As)[GBM][SPAD] = (__nv_bfloat16(*)[GBM][SPAD])dsm;
    __nv_bfloat16 (*Bs)[GBN][SPAD] = (__nv_bfloat16(*)[GBN][SPAD])(dsm + AS_BYTES);
    float (*zbuf)[ZB_STRIDE] = (float(*)[ZB_STRIDE])(dsm + AB_BYTES);
    float (*usm)[US_STRIDE] = (float(*)[US_STRIDE])(dsm + AB_BYTES + ZB_BYTES);

    int by = blockIdx.y, bx = blockIdx.x;
    int bm = by * GBM;
    int bn = bx * GBN;
    int tid = threadIdx.x;
    int wid = tid >> 5, lane = tid & 31;
    int wm = wid & 3, wn = wid >> 2;      // 4 x 2 warps; warp tile 16 x 56
    int g = lane >> 2, tg = lane & 3;

    float acc[7][4] = {};

    auto load_stage = [&](int it, int buf) {
        int k0 = it * GBK;
        {
            int row = tid >> 2, cg = tid & 3;
            int kk = k0 + 8 * cg;
            const __nv_bfloat16* src = g_xh + (size_t)(bm + row) * DD + kk;
            cp16(smem_u32(&As[buf][row][8 * cg]), src, (kk < DD) ? 16 : 0);
        }
#pragma unroll
        for (int ii = 0; ii < 2; ii++) {
            int task = tid + ii * 256;
            if (task < 448) {
                int row = task >> 2, cg = task & 3;
                int kk = k0 + 8 * cg;
                const __nv_bfloat16* src = W + (size_t)(bn + row) * DD + kk;
                cp16(smem_u32(&Bs[buf][row][8 * cg]), src, (kk < DD) ? 16 : 0);
            }
        }
        asm volatile("cp.async.commit_group;\n");
    };

    load_stage(0, 0);
    for (int it = 0; it < NIT; it++) {
        int buf = it & 1;
        if (it + 1 < NIT) {
            load_stage(it + 1, buf ^ 1);
            asm volatile("cp.async.wait_group 1;\n");
        } else {
            asm volatile("cp.async.wait_group 0;\n");
        }
        __syncthreads();
#pragma unroll
        for (int kh = 0; kh < 2; kh++) {
            int kk = 16 * kh;
            int r0 = wm * 16 + g;
            unsigned a0 = *(const unsigned*)&As[buf][r0][kk + 2 * tg];
            unsigned a1 = *(const unsigned*)&As[buf][r0 + 8][kk + 2 * tg];
            unsigned a2 = *(const unsigned*)&As[buf][r0][kk + 2 * tg + 8];
            unsigned a3 = *(const unsigned*)&As[buf][r0 + 8][kk + 2 * tg + 8];
#pragma unroll
            for (int j = 0; j < 7; j++) {
                int nr = wn * 56 + j * 8 + g;
                unsigned b0 = *(const unsigned*)&Bs[buf][nr][kk + 2 * tg];
                unsigned b1 = *(const unsigned*)&Bs[buf][nr][kk + 2 * tg + 8];
                asm volatile(
                    "mma.sync.aligned.m16n8k16.row.col.f32.bf16.bf16.f32 "
                    "{%0,%1,%2,%3}, {%4,%5,%6,%7}, {%8,%9}, {%0,%1,%2,%3};"
                    : "+f"(acc[j][0]), "+f"(acc[j][1]), "+f"(acc[j][2]), "+f"(acc[j][3])
                    : "r"(a0), "r"(a1), "r"(a2), "r"(a3), "r"(b0), "r"(b1));
            }
        }
        __syncthreads();
    }

    // ---- epilogue A: z = relu(acc + b) -> zbuf; u slice -> usm ----
    {
        int sr0 = wm * 16 + g;
        int sr1 = sr0 + 8;
#pragma unroll
        for (int j = 0; j < 7; j++) {
            int cl = wn * 56 + j * 8 + 2 * tg;
            float b0 = bias ? bias[bn + cl] : 0.f;
            float b1 = bias ? bias[bn + cl + 1] : 0.f;
            float v00 = acc[j][0] + b0, v01 = acc[j][1] + b1;
            float v10 = acc[j][2] + b0, v11 = acc[j][3] + b1;
            if (do_relu) {
                v00 = fmaxf(v00, 0.f); v01 = fmaxf(v01, 0.f);
                v10 = fmaxf(v10, 0.f); v11 = fmaxf(v11, 0.f);
            }
            zbuf[sr0][cl] = v00; zbuf[sr0][cl + 1] = v01;
            zbuf[sr1][cl] = v10; zbuf[sr1][cl + 1] = v11;
        }
    }
    // u slice: dY rows 4bx..4bx+3 -> 40 floats/sample (64 x 40 = 2560 tasks)
#pragma unroll
    for (int ii = 0; ii < 10; ii++) {
        int e = tid + 256 * ii;
        int sr = e / 40, q = e % 40;
        usm[sr][q] = X[(size_t)(bm + sr) * 840 + bx * 40 + q];
    }
    __syncthreads();

    // ---- epilogue B: partial P -> slab (coalesced, no atomics) ----
    {
        float* slab = g_Pp + (size_t)bx * N_SAMP * 280 + (size_t)bm * 280;
        for (int e = tid; e < GBM * 280; e += 256) {
            int sr = e / 280, rem = e % 280;
            int a = rem / 28, c = rem % 28;
            float val = 0.f;
#pragma unroll
            for (int rl = 0; rl < 4; rl++)
                val += usm[sr][rl * 10 + a] * zbuf[sr][rl * 28 + c];
            slab[(size_t)sr * 280 + rem] = val;
        }
    }
    __threadfence();
    __syncthreads();

    // ---- handoff: wait for all 7 column blocks of this bm row ----
    int* cnt = g_cnt + col * 32 + by;
    if (tid == 0) {
        atomicAdd(cnt, 1);
        while (atomicAdd(cnt, 0) < 7) { __nanosleep(40); }
        __threadfence();
    }
    __syncthreads();

    // ---- phase 2: update s and x for this block's ~9-sample slice ----
    float* fb = (float*)dsm;               // 8 warps x 1220 floats = 39KB
    float* u  = fb + wid * 1220;
    float* v  = u + 280;
    float* P  = v + 280;
    float* US = P + 280;
    float* s  = US + 280;

    int lo = (bx * GBM) / 7, hi = ((bx + 1) * GBM) / 7;
    for (int jj = lo + wid; jj < hi; jj += 8) {
        int i = bm + jj;
        const float* xb = X + (size_t)i * 840;
        for (int k = lane; k < 280; k += 32) { u[k] = xb[k]; v[k] = xb[560 + k]; }
        for (int k = lane; k < 100; k += 32) s[k] = g_s[i * 100 + k];
        for (int k = lane; k < 280; k += 32) {
            float a0 = 0.f;
#pragma unroll
            for (int b = 0; b < 7; b++)
                a0 += __ldcg(g_Pp + (size_t)b * N_SAMP * 280 + (size_t)i * 280 + k);
            P[k] = a0;
        }
        __syncwarp();
        for (int k = lane; k < 100; k += 32) {
            int a = k / 10, b = k % 10;
            float a0 = 0.f;
#pragma unroll
            for (int c = 0; c < 28; c++) a0 += P[a * 28 + c] * v[b * 28 + c];
            float sn = s[k] + HCONST * a0;
            s[k] = sn;
            g_s[i * 100 + k] = sn;
            g_shist[(size_t)col * N_SAMP * 100 + (size_t)i * 100 + k] = sn;
        }
        __syncwarp();
        for (int k = lane; k < 280; k += 32) {
            int r = k / 10, b = k % 10;
            float a0 = 0.f;
#pragma unroll
            for (int a = 0; a < 10; a++) a0 += u[r * 10 + a] * s[a * 10 + b];
            US[k] = a0;
        }
        __syncwarp();
        __nv_bfloat162* xdst = (__nv_bfloat162*)(g_xh + (size_t)i * DD);
        for (int p = lane; p < 392; p += 32) {
            int r = p / 14, cc = (p % 14) * 2;
            float a0 = 0.f, a1 = 0.f;
#pragma unroll
            for (int b = 0; b < 10; b++) {
                float us = US[r * 10 + b];
                a0 += us * v[b * 28 + cc];
                a1 += us * v[b * 28 + cc + 1];
            }
            xdst[p] = __float22bfloat162_rn(make_float2(a0, a1));
        }
        __syncwarp();
    }
}

// ---------------- expand: trans[i][k][l] from s_hist -------------------------
__global__ __launch_bounds__(256) void expand_kernel(const float* __restrict__ X,
                                                     float* __restrict__ trans) {
    __shared__ float u[280], vh[280], sall[3300], US[1320], xs[3696];
    int i = blockIdx.x, t = threadIdx.x;
    const float* xb = X + (size_t)i * 840;
    for (int k = t; k < 280; k += 256) { u[k] = xb[k]; vh[k] = xb[560 + k]; }
    for (int k = t; k < 3300; k += 256) {
        int l = k / 100, j = k % 100;
        sall[k] = g_shist[(size_t)l * N_SAMP * 100 + (size_t)i * 100 + j];
    }
    __syncthreads();
    float* base = trans + (size_t)i * (DD * 33);
    for (int ch = 0; ch < 7; ch++) {
        int r0 = ch * 4;
        for (int k = t; k < 1320; k += 256) {
            int l = k / 40, rem = k % 40, rr = rem / 10, b = rem % 10;
            float acc = 0.f;
#pragma unroll
            for (int a = 0; a < 10; a++) acc += u[(r0 + rr) * 10 + a] * sall[l * 100 + a * 10 + b];
            US[k] = acc;
        }
        __syncthreads();
        for (int k = t; k < 3696; k += 256) {
            int l = k / 112, kk = k % 112, rr = kk / 28, c = kk % 28;
            float acc = 0.f;
#pragma unroll
            for (int b = 0; b < 10; b++) acc += US[l * 40 + rr * 10 + b] * vh[b * 28 + c];
            xs[k] = acc;
        }
        __syncthreads();
        for (int e = t; e < 3696; e += 256) {
            base[ch * 3696 + e] = xs[(e % 33) * 112 + e / 33];
        }
        __syncthreads();
    }
}

// ---------------- classify ---------------------------------------------------
__global__ __launch_bounds__(128) void classify_kernel(const float* __restrict__ X,
                                                       const float* __restrict__ Wc,
                                                       const float* __restrict__ bc,
                                                       float* __restrict__ pred,
                                                       float* __restrict__ cls) {
    __shared__ float u[280], vh[280], s[100], US[280], x[784], lgs[KCLS];
    int i = blockIdx.x, t = threadIdx.x;
    int w = t >> 5, lane = t & 31;
    const float* xb = X + (size_t)i * 840;
    for (int k = t; k < 280; k += 128) { u[k] = xb[k]; vh[k] = xb[560 + k]; }
    for (int k = t; k < 100; k += 128) s[k] = g_s[i * 100 + k];
    __syncthreads();
    for (int k = t; k < 280; k += 128) {
        int r = k / 10, b = k % 10;
        float acc = 0.f;
#pragma unroll
        for (int a = 0; a < 10; a++) acc += u[r * 10 + a] * s[a * 10 + b];
        US[k] = acc;
    }
    __syncthreads();
    for (int k = t; k < 784; k += 128) {
        int r = k / 28, c = k % 28;
        float acc = 0.f;
#pragma unroll
        for (int b = 0; b < 10; b++) acc += US[r * 10 + b] * vh[b * 28 + c];
        x[k] = acc;
    }
    __syncthreads();
    for (int c = w; c < KCLS; c += 4) {
        const float* wr = Wc + (size_t)c * DD;
        float acc = 0.f;
#pragma unroll
        for (int it = 0; it < 25; it++) {
            int k = lane + 32 * it;
            if (k < 784) acc += x[k] * wr[k];
        }
#pragma unroll
        for (int o = 16; o; o >>= 1) acc += __shfl_down_sync(0xffffffffu, acc, o);
        if (lane == 0) lgs[c] = acc + bc[c];
    }
    __syncthreads();
    if (t == 0) {
        float mx = -1e30f;
#pragma unroll
        for (int c = 0; c < KCLS; c++) {
            cls[(size_t)i * KCLS + c] = lgs[c];
            if (lgs[c] > mx) mx = lgs[c];
        }
        float e[KCLS], ssum = 0.f;
#pragma unroll
        for (int c = 0; c < KCLS; c++) { e[c] = expf(lgs[c] - mx); ssum += e[c]; }
        float inv = 1.f / ssum;
#pragma unroll
        for (int c = 0; c < KCLS; c++) pred[(size_t)i * KCLS + c] = e[c] * inv;
    }
}

// ---------------- launcher ---------------------------------------------------
extern "C" void kernel_launch(void* const* d_in, const int* in_sizes, int n_in,
                              void* d_out, int out_size) {
    const float* X  = (const float*)d_in[0];
    const float* W0 = (const float*)d_in[1];
    const float* Ws = (const float*)d_in[2];
    const float* bs = (const float*)d_in[3];
    const float* Wc = (const float*)d_in[4];
    const float* bc = (const float*)d_in[5];
    float* out = (float*)d_out;
    float* pred  = out;
    float* cls   = out + (size_t)N_SAMP * KCLS;
    float* trans = out + (size_t)2 * N_SAMP * KCLS;

    static const __nv_bfloat16* wh_dev = nullptr;
    static bool configured = false;
    if (!configured) {
        void* p = nullptr;
        cudaGetSymbolAddress(&p, g_wh);
        wh_dev = (const __nv_bfloat16*)p;
        cudaFuncSetAttribute(layer_kernel, cudaFuncAttributeMaxDynamicSharedMemorySize, LAYER_SMEM);
        configured = true;
    }

    {
        size_t total = (size_t)33 * DD * DD;
        int blocks = (int)((total / 4 + 255) / 256);
        wcvt_kernel<<<blocks, 256>>>(W0, Ws);
    }
    init_kernel<<<N_SAMP, 256>>>(X);

    dim3 ggrid(DD / GBN, N_SAMP / GBM);   // (7, 32) = 224 blocks, all co-resident
    for (int col = 0; col < 33; col++) {
        const __nv_bfloat16* W = wh_dev + (size_t)col * DD * DD;
        const float* bias = (col > 0) ? (bs + (size_t)(col - 1) * DD) : nullptr;
        layer_kernel<<<ggrid, 256, LAYER_SMEM>>>(X, W, bias, col > 0 ? 1 : 0, col);
    }
    expand_kernel<<<N_SAMP, 256>>>(X, trans);
    classify_kernel<<<N_SAMP, 128>>>(X, Wc, bc, pred, cls);
}

// round 11
// speedup vs baseline: 1.3814x; 1.3814x over previous
#include <cuda_runtime.h>
#include <cuda_bf16.h>
#include <cstdint>
#include <math.h>

#define N_SAMP 2048
#define DD 784
#define KR 10
#define LAYERS 32
#define KCLS 10
#define HCONST 0.001f

__device__ float g_s[N_SAMP * 100];
__device__ float g_shist[33 * N_SAMP * 100];
__device__ __nv_bfloat16 g_xh[N_SAMP * DD];
__device__ float g_z[N_SAMP * DD];
__device__ __nv_bfloat16 g_wh[33 * DD * DD];

// ---------------- weights -> bf16 -------------------------------------------
__global__ void wcvt_kernel(const float* __restrict__ W0, const float* __restrict__ Ws) {
    size_t idx = ((size_t)blockIdx.x * blockDim.x + threadIdx.x) * 4;
    size_t total = (size_t)33 * DD * DD;
    if (idx >= total) return;
    size_t per = (size_t)DD * DD;
    const float* src = (idx < per) ? (W0 + idx) : (Ws + (idx - per));
    float4 v = *(const float4*)src;
    __nv_bfloat16 o[4] = {__float2bfloat16(v.x), __float2bfloat16(v.y),
                          __float2bfloat16(v.z), __float2bfloat16(v.w)};
    *(uint2*)(g_wh + idx) = *(uint2*)o;
}

// ---------------- init -------------------------------------------------------
__global__ void init_kernel(const float* __restrict__ X) {
    __shared__ float u[280], vh[280], s[100], US[280];
    int i = blockIdx.x, t = threadIdx.x;
    const float* xb = X + (size_t)i * 840;
    for (int k = t; k < 280; k += blockDim.x) { u[k] = xb[k]; vh[k] = xb[560 + k]; }
    for (int k = t; k < 100; k += blockDim.x) { float v = xb[280 + k]; s[k] = v; g_s[i * 100 + k] = v; }
    __syncthreads();
    for (int k = t; k < 280; k += blockDim.x) {
        int r = k / 10, b = k % 10;
        float acc = 0.f;
#pragma unroll
        for (int a = 0; a < 10; a++) acc += u[r * 10 + a] * s[a * 10 + b];
        US[k] = acc;
    }
    __syncthreads();
    for (int k = t; k < DD; k += blockDim.x) {
        int r = k / 28, c = k % 28;
        float acc = 0.f;
#pragma unroll
        for (int b = 0; b < 10; b++) acc += US[r * 10 + b] * vh[b * 28 + c];
        g_xh[(size_t)i * DD + k] = __float2bfloat16(acc);
    }
}

// ---------------- GEMM: g_z = relu(g_xh @ W^T + b), BM=128 BK=64 ------------
#define GBM 128
#define GBN 112
#define GBK 64
#define SPAD 72
#define NIT 13   // ceil(784/64); tail zero-filled by cp.async sz=0

__device__ __forceinline__ unsigned smem_u32(const void* p) {
    return (unsigned)__cvta_generic_to_shared(p);
}
__device__ __forceinline__ void cp16(unsigned dst, const void* src, int sz) {
    asm volatile("cp.async.cg.shared.global [%0], [%1], 16, %2;\n"
                 :: "r"(dst), "l"(src), "r"(sz));
}

__global__ __launch_bounds__(256) void gemm_tc_kernel(const __nv_bfloat16* __restrict__ W,
                                                      const float* __restrict__ bias,
                                                      int do_relu) {
    __shared__ __nv_bfloat16 As[2][GBM][SPAD];
    __shared__ __nv_bfloat16 Bs[2][GBN][SPAD];
    int bm = blockIdx.y * GBM;
    int bn = blockIdx.x * GBN;
    int tid = threadIdx.x;
    int wid = tid >> 5, lane = tid & 31;
    int wm = wid & 3, wn = wid >> 2;      // 4 x 2 warps; warp tile 32 x 56
    int g = lane >> 2, tg = lane & 3;

    float acc[2][7][4] = {};

    auto load_stage = [&](int it, int buf) {
        int k0 = it * GBK;
        // A: 128 rows x 8 chunks of 16B = 1024 tasks
#pragma unroll
        for (int ii = 0; ii < 4; ii++) {
            int task = tid + ii * 256;
            int row = task >> 3, cg = task & 7;
            int kk = k0 + 8 * cg;
            const __nv_bfloat16* src = g_xh + (size_t)(bm + row) * DD + kk;
            cp16(smem_u32(&As[buf][row][8 * cg]), src, (kk < DD) ? 16 : 0);
        }
        // B: 112 rows x 8 chunks = 896 tasks
#pragma unroll
        for (int ii = 0; ii < 4; ii++) {
            int task = tid + ii * 256;
            if (task < 896) {
                int row = task >> 3, cg = task & 7;
                int kk = k0 + 8 * cg;
                const __nv_bfloat16* src = W + (size_t)(bn + row) * DD + kk;
                cp16(smem_u32(&Bs[buf][row][8 * cg]), src, (kk < DD) ? 16 : 0);
            }
        }
        asm volatile("cp.async.commit_group;\n");
    };

    load_stage(0, 0);
    for (int it = 0; it < NIT; it++) {
        int buf = it & 1;
        if (it + 1 < NIT) {
            load_stage(it + 1, buf ^ 1);
            asm volatile("cp.async.wait_group 1;\n");
        } else {
            asm volatile("cp.async.wait_group 0;\n");
        }
        __syncthreads();
#pragma unroll
        for (int kh = 0; kh < 4; kh++) {
            int kk = 16 * kh;
            unsigned a[2][4];
#pragma unroll
            for (int mi = 0; mi < 2; mi++) {
                int r0 = wm * 32 + mi * 16 + g;
                a[mi][0] = *(const unsigned*)&As[buf][r0][kk + 2 * tg];
                a[mi][1] = *(const unsigned*)&As[buf][r0 + 8][kk + 2 * tg];
                a[mi][2] = *(const unsigned*)&As[buf][r0][kk + 2 * tg + 8];
                a[mi][3] = *(const unsigned*)&As[buf][r0 + 8][kk + 2 * tg + 8];
            }
#pragma unroll
            for (int j = 0; j < 7; j++) {
                int nr = wn * 56 + j * 8 + g;
                unsigned b0 = *(const unsigned*)&Bs[buf][nr][kk + 2 * tg];
                unsigned b1 = *(const unsigned*)&Bs[buf][nr][kk + 2 * tg + 8];
#pragma unroll
                for (int mi = 0; mi < 2; mi++) {
                    asm volatile(
                        "mma.sync.aligned.m16n8k16.row.col.f32.bf16.bf16.f32 "
                        "{%0,%1,%2,%3}, {%4,%5,%6,%7}, {%8,%9}, {%0,%1,%2,%3};"
                        : "+f"(acc[mi][j][0]), "+f"(acc[mi][j][1]),
                          "+f"(acc[mi][j][2]), "+f"(acc[mi][j][3])
                        : "r"(a[mi][0]), "r"(a[mi][1]), "r"(a[mi][2]), "r"(a[mi][3]),
                          "r"(b0), "r"(b1));
                }
            }
        }
        __syncthreads();
    }
#pragma unroll
    for (int mi = 0; mi < 2; mi++) {
        int row0 = bm + wm * 32 + mi * 16 + g;
        int row1 = row0 + 8;
#pragma unroll
        for (int j = 0; j < 7; j++) {
            int col = bn + wn * 56 + j * 8 + 2 * tg;
            float b0 = bias ? bias[col] : 0.f;
            float b1 = bias ? bias[col + 1] : 0.f;
            float2 v0 = make_float2(acc[mi][j][0] + b0, acc[mi][j][1] + b1);
            float2 v1 = make_float2(acc[mi][j][2] + b0, acc[mi][j][3] + b1);
            if (do_relu) {
                v0.x = fmaxf(v0.x, 0.f); v0.y = fmaxf(v0.y, 0.f);
                v1.x = fmaxf(v1.x, 0.f); v1.y = fmaxf(v1.y, 0.f);
            }
            *(float2*)(g_z + (size_t)row0 * DD + col) = v0;
            *(float2*)(g_z + (size_t)row1 * DD + col) = v1;
        }
    }
}

// ---------------- update: 128 threads/sample, 2 samples/block (R9, 16.1us) --
__global__ __launch_bounds__(256) void update_kernel(const float* __restrict__ X, int col) {
    __shared__ float su[2][280], svh[2][280], sdY[2][784], sP[2][280], ss[2][104], sUS[2][280];
    int t = threadIdx.x;
    int w = t >> 7;
    int tl = t & 127;
    int i = blockIdx.x * 2 + w;
    const float* xb = X + (size_t)i * 840;
#pragma unroll
    for (int it = 0; it < 3; it++) {
        int k = tl + 128 * it;
        if (k < 280) { su[w][k] = xb[k]; svh[w][k] = xb[560 + k]; }
    }
    const float* zsrc = g_z + (size_t)i * DD;
#pragma unroll
    for (int it = 0; it < 7; it++) {
        int k = tl + 128 * it;
        if (k < 784) sdY[w][k] = zsrc[k];
    }
    if (tl < 100) ss[w][tl] = g_s[i * 100 + tl];
    __syncthreads();
#pragma unroll
    for (int it = 0; it < 3; it++) {
        int k = tl + 128 * it;
        if (k < 280) {
            int a = k / 28, c = k % 28;
            float acc = 0.f;
#pragma unroll
            for (int r = 0; r < 28; r++) acc += su[w][r * 10 + a] * sdY[w][r * 28 + c];
            sP[w][k] = acc;
        }
    }
    __syncthreads();
    if (tl < 100) {
        int a = tl / 10, b = tl % 10;
        float acc = 0.f;
#pragma unroll
        for (int c = 0; c < 28; c++) acc += sP[w][a * 28 + c] * svh[w][b * 28 + c];
        float sn = ss[w][tl] + HCONST * acc;
        ss[w][tl] = sn;
        g_s[i * 100 + tl] = sn;
        g_shist[(size_t)col * N_SAMP * 100 + (size_t)i * 100 + tl] = sn;
    }
    __syncthreads();
#pragma unroll
    for (int it = 0; it < 3; it++) {
        int k = tl + 128 * it;
        if (k < 280) {
            int r = k / 10, b = k % 10;
            float acc = 0.f;
#pragma unroll
            for (int a = 0; a < 10; a++) acc += su[w][r * 10 + a] * ss[w][a * 10 + b];
            sUS[w][k] = acc;
        }
    }
    __syncthreads();
    __nv_bfloat162* xdst = (__nv_bfloat162*)(g_xh + (size_t)i * DD);
#pragma unroll
    for (int it = 0; it < 4; it++) {
        int p = tl + 128 * it;
        if (p < 392) {
            int r = p / 14, cc = (p % 14) * 2;
            float a0 = 0.f, a1 = 0.f;
#pragma unroll
            for (int b = 0; b < 10; b++) {
                float us = sUS[w][r * 10 + b];
                a0 += us * svh[w][b * 28 + cc];
                a1 += us * svh[w][b * 28 + cc + 1];
            }
            xdst[p] = __float22bfloat162_rn(make_float2(a0, a1));
        }
    }
}

// ---------------- expand: trans[i][k][l] from s_hist -------------------------
__global__ __launch_bounds__(256) void expand_kernel(const float* __restrict__ X,
                                                     float* __restrict__ trans) {
    __shared__ float u[280], vh[280], sall[3300], US[1320], xs[3696];
    int i = blockIdx.x, t = threadIdx.x;
    const float* xb = X + (size_t)i * 840;
    for (int k = t; k < 280; k += 256) { u[k] = xb[k]; vh[k] = xb[560 + k]; }
    for (int k = t; k < 3300; k += 256) {
        int l = k / 100, j = k % 100;
        sall[k] = g_shist[(size_t)l * N_SAMP * 100 + (size_t)i * 100 + j];
    }
    __syncthreads();
    float* base = trans + (size_t)i * (DD * 33);
    for (int ch = 0; ch < 7; ch++) {
        int r0 = ch * 4;
        for (int k = t; k < 1320; k += 256) {
            int l = k / 40, rem = k % 40, rr = rem / 10, b = rem % 10;
            float acc = 0.f;
#pragma unroll
            for (int a = 0; a < 10; a++) acc += u[(r0 + rr) * 10 + a] * sall[l * 100 + a * 10 + b];
            US[k] = acc;
        }
        __syncthreads();
        for (int k = t; k < 3696; k += 256) {
            int l = k / 112, kk = k % 112, rr = kk / 28, c = kk % 28;
            float acc = 0.f;
#pragma unroll
            for (int b = 0; b < 10; b++) acc += US[l * 40 + rr * 10 + b] * vh[b * 28 + c];
            xs[k] = acc;
        }
        __syncthreads();
        for (int e = t; e < 3696; e += 256) {
            base[ch * 3696 + e] = xs[(e % 33) * 112 + e / 33];
        }
        __syncthreads();
    }
}

// ---------------- classify ---------------------------------------------------
__global__ __launch_bounds__(128) void classify_kernel(const float* __restrict__ X,
                                                       const float* __restrict__ Wc,
                                                       const float* __restrict__ bc,
                                                       float* __restrict__ pred,
                                                       float* __restrict__ cls) {
    __shared__ float u[280], vh[280], s[100], US[280], x[784], lgs[KCLS];
    int i = blockIdx.x, t = threadIdx.x;
    int w = t >> 5, lane = t & 31;
    const float* xb = X + (size_t)i * 840;
    for (int k = t; k < 280; k += 128) { u[k] = xb[k]; vh[k] = xb[560 + k]; }
    for (int k = t; k < 100; k += 128) s[k] = g_s[i * 100 + k];
    __syncthreads();
    for (int k = t; k < 280; k += 128) {
        int r = k / 10, b = k % 10;
        float acc = 0.f;
#pragma unroll
        for (int a = 0; a < 10; a++) acc += u[r * 10 + a] * s[a * 10 + b];
        US[k] = acc;
    }
    __syncthreads();
    for (int k = t; k < 784; k += 128) {
        int r = k / 28, c = k % 28;
        float acc = 0.f;
#pragma unroll
        for (int b = 0; b < 10; b++) acc += US[r * 10 + b] * vh[b * 28 + c];
        x[k] = acc;
    }
    __syncthreads();
    for (int c = w; c < KCLS; c += 4) {
        const float* wr = Wc + (size_t)c * DD;
        float acc = 0.f;
#pragma unroll
        for (int it = 0; it < 25; it++) {
            int k = lane + 32 * it;
            if (k < 784) acc += x[k] * wr[k];
        }
#pragma unroll
        for (int o = 16; o; o >>= 1) acc += __shfl_down_sync(0xffffffffu, acc, o);
        if (lane == 0) lgs[c] = acc + bc[c];
    }
    __syncthreads();
    if (t == 0) {
        float mx = -1e30f;
#pragma unroll
        for (int c = 0; c < KCLS; c++) {
            cls[(size_t)i * KCLS + c] = lgs[c];
            if (lgs[c] > mx) mx = lgs[c];
        }
        float e[KCLS], ssum = 0.f;
#pragma unroll
        for (int c = 0; c < KCLS; c++) { e[c] = expf(lgs[c] - mx); ssum += e[c]; }
        float inv = 1.f / ssum;
#pragma unroll
        for (int c = 0; c < KCLS; c++) pred[(size_t)i * KCLS + c] = e[c] * inv;
    }
}

// ---------------- launcher ---------------------------------------------------
extern "C" void kernel_launch(void* const* d_in, const int* in_sizes, int n_in,
                              void* d_out, int out_size) {
    const float* X  = (const float*)d_in[0];
    const float* W0 = (const float*)d_in[1];
    const float* Ws = (const float*)d_in[2];
    const float* bs = (const float*)d_in[3];
    const float* Wc = (const float*)d_in[4];
    const float* bc = (const float*)d_in[5];
    float* out = (float*)d_out;
    float* pred  = out;
    float* cls   = out + (size_t)N_SAMP * KCLS;
    float* trans = out + (size_t)2 * N_SAMP * KCLS;

    static const __nv_bfloat16* wh_dev = nullptr;
    if (!wh_dev) {
        void* p = nullptr;
        cudaGetSymbolAddress(&p, g_wh);
        wh_dev = (const __nv_bfloat16*)p;
    }

    {
        size_t total = (size_t)33 * DD * DD;
        int blocks = (int)((total / 4 + 255) / 256);
        wcvt_kernel<<<blocks, 256>>>(W0, Ws);
    }
    init_kernel<<<N_SAMP, 256>>>(X);

    dim3 ggrid(DD / GBN, N_SAMP / GBM);   // (7, 16) = 112 blocks
    for (int col = 0; col < 33; col++) {
        const __nv_bfloat16* W = wh_dev + (size_t)col * DD * DD;
        const float* bias = (col > 0) ? (bs + (size_t)(col - 1) * DD) : nullptr;
        gemm_tc_kernel<<<ggrid, 256>>>(W, bias, col > 0 ? 1 : 0);
        update_kernel<<<N_SAMP / 2, 256>>>(X, col);
    }
    expand_kernel<<<N_SAMP, 256>>>(X, trans);
    classify_kernel<<<N_SAMP, 128>>>(X, Wc, bc, pred, cls);
}